// round 13
// baseline (speedup 1.0000x reference)
#include <cuda_runtime.h>
#include <cuda_bf16.h>
#include <cstdint>

// B=8, N=2048, FEAT=16, pos = feats [0,2), radius = 0.25.
// Output [B, N, N] fp32 mask = 128 MiB stores. Main kernel is issue-bound
// (STG.128 ~12cyc issue + predicate math). 75% of columns lie outside the
// active window [T, T+tau) -> pure-zero stores need NO compute. Specialized
// zero-store / compute passes cut issued instructions ~2x.
static constexpr int N_     = 2048;
static constexpr int BATCH_ = 8;
static constexpr int R_ROWS = 32;          // rows per block
static constexpr float R2   = 0.0625f;     // 0.25^2

__device__ __align__(16) float2 g_pos[BATCH_][N_];

__device__ __forceinline__ int read_idx_arr(const int* __restrict__ a32, int b)
{
    // Handles both int32 and int64(small values) materialization of T/taus.
    const bool is64 = (a32[1] == 0) && (a32[0] != 0);
    return is64 ? a32[2 * b] : a32[b];
}

__global__ void __launch_bounds__(128)
compact_kernel(const float* __restrict__ nodes)
{
    const int node = blockIdx.x * 128 + threadIdx.x;   // 128 blocks x 128 = 16384
    const float2 p = *(const float2*)(nodes + (size_t)node * 16);
    reinterpret_cast<float2*>(g_pos)[node] = p;        // coalesced 8B store
}

__global__ void __launch_bounds__(256)
radius_edge_kernel(const int* __restrict__ T_arr,
                   const int* __restrict__ tau_arr,
                   float4* __restrict__ out)
{
    // grid = B * (N / R_ROWS) = 8 * 64 = 512 blocks x 256 threads.
    const int b  = blockIdx.x >> 6;            // /64
    const int i0 = (blockIdx.x & 63) * R_ROWS;
    const int t  = threadIdx.x;

    const int Tlo = read_idx_arr(T_arr, b);
    const int Thi = Tlo + read_idx_arr(tau_arr, b);  // active cols [Tlo, Thi)

    float4* orow = out + ((size_t)b * N_ + i0) * (N_ / 4);
    const float4 zero = make_float4(0.f, 0.f, 0.f, 0.f);

    // ---- Pass A: columns [4t, 4t+4) ----
    {
        const int j0 = 4 * t;
        if (j0 + 3 >= Tlo && j0 < Thi) {
            // Active group (~25% of threads, warp-uniform): full compute.
            const float4* pbase = reinterpret_cast<const float4*>(&g_pos[b][0]);
            const float4 r0 = pbase[2 * t];
            const float4 r1 = pbase[2 * t + 1];
            const float px[4] = {r0.x, r0.z, r1.x, r1.z};
            const float py[4] = {r0.y, r0.w, r1.y, r1.w};
            bool w[4];
            #pragma unroll
            for (int k = 0; k < 4; k++)
                w[k] = (j0 + k >= Tlo) && (j0 + k < Thi);

            #pragma unroll 4
            for (int r = 0; r < R_ROWS; r++) {
                const int i = i0 + r;
                const float2 pi = g_pos[b][i];   // broadcast, L1 hit
                float4 v;
                #pragma unroll
                for (int k = 0; k < 4; k++) {
                    const float dx = pi.x - px[k];
                    const float dy = pi.y - py[k];
                    const bool  c  = w[k] & (i < j0 + k) &
                                     (fmaf(dx, dx, dy * dy) < R2);
                    (&v.x)[k] = c ? 1.0f : 0.0f;
                }
                orow[(size_t)r * (N_ / 4) + t] = v;
            }
        } else {
            // Dead group: pure store stream, zero compute.
            #pragma unroll
            for (int r = 0; r < R_ROWS; r++)
                orow[(size_t)r * (N_ / 4) + t] = zero;
        }
    }

    // ---- Pass B: columns [4t+1024, 4t+1028) ----
    {
        const int j0 = 4 * t + 1024;
        const int tb = t + 256;
        if (j0 + 3 >= Tlo && j0 < Thi) {
            const float4* pbase = reinterpret_cast<const float4*>(&g_pos[b][0]);
            const float4 r0 = pbase[2 * tb];
            const float4 r1 = pbase[2 * tb + 1];
            const float px[4] = {r0.x, r0.z, r1.x, r1.z};
            const float py[4] = {r0.y, r0.w, r1.y, r1.w};
            bool w[4];
            #pragma unroll
            for (int k = 0; k < 4; k++)
                w[k] = (j0 + k >= Tlo) && (j0 + k < Thi);

            #pragma unroll 4
            for (int r = 0; r < R_ROWS; r++) {
                const int i = i0 + r;
                const float2 pi = g_pos[b][i];
                float4 v;
                #pragma unroll
                for (int k = 0; k < 4; k++) {
                    const float dx = pi.x - px[k];
                    const float dy = pi.y - py[k];
                    const bool  c  = w[k] & (i < j0 + k) &
                                     (fmaf(dx, dx, dy * dy) < R2);
                    (&v.x)[k] = c ? 1.0f : 0.0f;
                }
                orow[(size_t)r * (N_ / 4) + tb] = v;
            }
        } else {
            #pragma unroll
            for (int r = 0; r < R_ROWS; r++)
                orow[(size_t)r * (N_ / 4) + tb] = zero;
        }
    }
}

extern "C" void kernel_launch(void* const* d_in, const int* in_sizes, int n_in,
                              void* d_out, int out_size)
{
    const float* nodes   = (const float*)d_in[0];
    const int*   T_arr   = (const int*)d_in[1];
    const int*   tau_arr = (const int*)d_in[2];
    // d_in[3] = B scalar, unused (compile-time constants)

    compact_kernel<<<128, 128>>>(nodes);         // 16384 nodes, 1 thread each

    const int blocks = BATCH_ * (N_ / R_ROWS);   // 512
    radius_edge_kernel<<<blocks, 256>>>(T_arr, tau_arr, (float4*)d_out);
}